// round 6
// baseline (speedup 1.0000x reference)
#include <cuda_runtime.h>
#include <cstdint>

#define N_ANCH 36864
#define PRE    6000
#define NWORDS 94      /* ceil(6000/64) */
#define POST   300
#define NMS_T  0.7f
#define NEG_INF_F (-1e9f)
#define NBINS  65536
#define BPT    64      /* bins per thread in plan kernel (65536/1024) */

// ---------------- scratch (static device globals; no allocation) ----------------
__device__ float4             g_boxes[N_ANCH];          // decoded+clipped boxes
__device__ unsigned long long g_keyfull[N_ANCH];        // (desc<<16)|idx
__device__ int                g_hist[NBINS];            // zero at load; plan re-zeroes
__device__ int                g_bin_base[NBINS];
__device__ int                g_bin_fill[NBINS];        // zero at load; plan re-zeroes
__device__ int                g_thresh_bin;
__device__ int                g_cand_total;
__device__ unsigned long long g_cand[N_ANCH];
__device__ float4             g_boxes_s[PRE];           // top-6000 boxes, score order
__device__ unsigned long long g_invalid_words[NWORDS];  // suppressed-at-start bits
__device__ unsigned long long g_mask[PRE * NWORDS];     // suppression bitmask (upper tri)

// ---------------- 1. decode + clip + valid + key + histogram ----------------
__global__ void decode_kernel(const float* __restrict__ anchors,
                              const float* __restrict__ cls,
                              const float* __restrict__ reg,
                              const int* __restrict__ img_w_p,
                              const int* __restrict__ img_h_p,
                              int have_wh)
{
    int i = blockIdx.x * blockDim.x + threadIdx.x;
    if (i >= N_ANCH) return;

    float a0 = anchors[4*i+0], a1 = anchors[4*i+1];
    float a2 = anchors[4*i+2], a3 = anchors[4*i+3];
    float r0 = reg[4*i+0], r1 = reg[4*i+1], r2 = reg[4*i+2], r3 = reg[4*i+3];

    float w  = __fsub_rn(a2, a0);
    float h  = __fsub_rn(a3, a1);
    float cx = __fadd_rn(a0, __fmul_rn(0.5f, w));
    float cy = __fadd_rn(a1, __fmul_rn(0.5f, h));
    float pcx = __fadd_rn(__fmul_rn(r0, w), cx);
    float pcy = __fadd_rn(__fmul_rn(r1, h), cy);
    float pw  = __fmul_rn(expf(r2), w);
    float ph  = __fmul_rn(expf(r3), h);

    float b0 = __fsub_rn(pcx, __fmul_rn(0.5f, pw));
    float b1 = __fsub_rn(pcy, __fmul_rn(0.5f, ph));
    float b2 = __fadd_rn(pcx, __fmul_rn(0.5f, pw));
    float b3 = __fadd_rn(pcy, __fmul_rn(0.5f, ph));

    float H = have_wh ? (float)(*img_h_p) : 1024.0f;
    float W = have_wh ? (float)(*img_w_p) : 1024.0f;
    // reference: cols 0,2 clipped by img_h; cols 1,3 by img_w
    b0 = fminf(fmaxf(b0, 0.0f), H);
    b2 = fminf(fmaxf(b2, 0.0f), H);
    b1 = fminf(fmaxf(b1, 0.0f), W);
    b3 = fminf(fmaxf(b3, 0.0f), W);

    bool valid = (__fsub_rn(b2, b0) >= 16.0f) && (__fsub_rn(b3, b1) >= 16.0f);
    float s = valid ? cls[i] : NEG_INF_F;

    g_boxes[i] = make_float4(b0, b1, b2, b3);

    // stable descending sort key: smaller desc = higher score; idx breaks ties (stable)
    unsigned int bits = __float_as_uint(s);
    unsigned int asc  = (bits & 0x80000000u) ? ~bits : (bits | 0x80000000u);
    unsigned int desc = ~asc;
    unsigned long long key = ((unsigned long long)desc << 16) | (unsigned int)i;
    g_keyfull[i] = key;
    atomicAdd(&g_hist[desc >> 16], 1);
}

// ---------------- 2. plan: prefix-sum 65536 bins, find threshold, reset ----------------
// Two passes over each thread's 64 bins (L2-resident re-read) to keep regs low.
__global__ void __launch_bounds__(1024) plan_kernel()
{
    __shared__ int sp[1024];
    __shared__ int s_thresh;
    int t = threadIdx.x;
    if (t == 0) s_thresh = 0x7FFFFFFF;

    int b0 = t * BPT;
    int sum = 0;
    for (int k = 0; k < BPT; k++) sum += g_hist[b0 + k];
    sp[t] = sum;
    __syncthreads();
    // inclusive block scan over per-thread sums
    for (int off = 1; off < 1024; off <<= 1) {
        int v = (t >= off) ? sp[t - off] : 0;
        __syncthreads();
        sp[t] += v;
        __syncthreads();
    }
    int run = sp[t] - sum;                 // exclusive prefix for this thread's range
    bool straddle = (run < PRE) && (sp[t] >= PRE);
    for (int k = 0; k < BPT; k++) {
        int h = g_hist[b0 + k];            // re-read (L2 hit)
        g_bin_base[b0 + k] = run;
        run += h;
        if (straddle && run >= PRE && run - h < PRE) atomicMin(&s_thresh, b0 + k);
    }
    __syncthreads();
    if (t == 0) {
        int tb = s_thresh;
        g_thresh_bin = tb;
        g_cand_total = g_bin_base[tb] + g_hist[tb];
    }
    __syncthreads();   // t0 reads g_hist before zeroing
    for (int k = 0; k < BPT; k++) { g_hist[b0 + k] = 0; g_bin_fill[b0 + k] = 0; }
    if (t < NWORDS)
        g_invalid_words[t] = (t == NWORDS-1) ? ~((1ull << 48) - 1) : 0ull;  // ranks >= 6000
}

// ---------------- 3. scatter candidates into per-bin segments ----------------
__global__ void scatter_kernel()
{
    int i = blockIdx.x * blockDim.x + threadIdx.x;
    if (i >= N_ANCH) return;
    unsigned long long key = g_keyfull[i];
    int bin = (int)(key >> 32);
    if (bin <= g_thresh_bin) {
        int pos = g_bin_base[bin] + atomicAdd(&g_bin_fill[bin], 1);
        g_cand[pos] = key;
    }
}

// ---------------- 4. exact rank within bin + gather boxes ----------------
__global__ void rank_kernel()
{
    int c = blockIdx.x * blockDim.x + threadIdx.x;
    int tot = g_cand_total;
    if (c >= tot) return;
    unsigned long long key = g_cand[c];
    int bin = (int)(key >> 32);
    int b0 = g_bin_base[bin];
    int b1 = b0 + g_bin_fill[bin];
    int rank = b0;
    for (int j = b0; j < b1; j++)
        if (g_cand[j] < key) rank++;
    if (rank < PRE) {
        int idx = (int)(key & 0xFFFFull);
        g_boxes_s[rank] = g_boxes[idx];
        unsigned int desc = (unsigned int)(key >> 16);
        if (desc & 0x80000000u)   // invalid box -> pre-suppressed
            atomicOr(&g_invalid_words[rank >> 6], 1ull << (rank & 63));
    }
}

// ---------------- 5. NMS suppression bitmask (upper-triangle blocks only) ----------------
__global__ void mask_kernel()
{
    if (blockIdx.y < blockIdx.x) return;   // lower triangle never read by scan
    __shared__ float4 cb[64];
    __shared__ float  ca[64];
    int tid = threadIdx.x;
    int jb  = blockIdx.y;
    int j0  = jb * 64;
    int jj  = j0 + tid;
    float4 b = (jj < PRE) ? g_boxes_s[jj] : make_float4(0.f, 0.f, 0.f, 0.f);
    cb[tid] = b;
    ca[tid] = __fmul_rn(__fsub_rn(b.z, b.x), __fsub_rn(b.w, b.y));
    __syncthreads();

    int i = blockIdx.x * 64 + tid;
    if (i >= PRE) return;
    float4 bi = g_boxes_s[i];
    float  ai = __fmul_rn(__fsub_rn(bi.z, bi.x), __fsub_rn(bi.w, bi.y));

    unsigned long long m = 0;
#pragma unroll 8
    for (int s = 0; s < 64; s++) {
        int j = j0 + s;
        float4 bj = cb[s];
        float xx1 = fmaxf(bi.x, bj.x);
        float yy1 = fmaxf(bi.y, bj.y);
        float xx2 = fminf(bi.z, bj.z);
        float yy2 = fminf(bi.w, bj.w);
        float iw  = fmaxf(__fsub_rn(xx2, xx1), 0.0f);
        float ih  = fmaxf(__fsub_rn(yy2, yy1), 0.0f);
        float inter = __fmul_rn(iw, ih);
        // exact reference op order: ((ai + aj) - inter) + 1e-9, IEEE divide
        float den = __fadd_rn(__fsub_rn(__fadd_rn(ai, ca[s]), inter), 1e-9f);
        float iou = __fdiv_rn(inter, den);
        if ((iou > NMS_T) && (j > i)) m |= (1ull << s);
    }
    g_mask[i * NWORDS + jb] = m;
}

// ---------------- 6. greedy scan (chunked, parallel propagation) + output ----------------
__global__ void __launch_bounds__(1024) scan_kernel(float* __restrict__ out)
{
    __shared__ unsigned long long s_rem[NWORDS];
    __shared__ unsigned long long s_intra[64];
    __shared__ unsigned char     s_aliveb[64];
    __shared__ unsigned short    s_keep[POST];
    __shared__ int s_n, s_kept;
    int tid = threadIdx.x;

    if (tid < NWORDS) s_rem[tid] = g_invalid_words[tid];
    if (tid == 0) s_kept = 0;
    __syncthreads();

    for (int c = 0; c < NWORDS; c++) {
        if (tid < 64) {
            int i = c * 64 + tid;
            s_intra[tid] = (i < PRE) ? g_mask[i * NWORDS + c] : 0ull;
        }
        __syncthreads();

        if (tid == 0) {
            unsigned long long rem = s_rem[c];
            int n = 0;
            int kept = s_kept;
            unsigned long long m = ~rem;
            while (m) {
                int b = __ffsll((long long)m) - 1;    // smallest alive index
                s_keep[kept] = (unsigned short)(c * 64 + b);
                kept++;
                s_aliveb[n++] = (unsigned char)b;
                if (kept >= POST) break;
                rem |= s_intra[b];
                m = ~rem & (~0ull << (b + 1));        // alive bits strictly above b
            }
            s_n = n;
            s_kept = kept;
        }
        __syncthreads();

        if (s_kept >= POST) break;                    // output fixed; later chunks irrelevant
        if (c == NWORDS - 1) break;

        // parallel propagation: (alive bit) x (future word)
        int n  = s_n;
        int nw = NWORDS - 1 - c;
        for (int p = tid; p < n * nw; p += 1024) {
            int bi = p / nw;
            int w  = c + 1 + p - bi * nw;
            unsigned long long v = g_mask[(c * 64 + s_aliveb[bi]) * NWORDS + w];
            atomicOr(&s_rem[w], v);
        }
        __syncthreads();
    }
    __syncthreads();

    // write output: kept boxes in order, zero-pad the tail
    int kept = s_kept;
    if (tid < POST) {
        float4 v = make_float4(0.f, 0.f, 0.f, 0.f);
        if (tid < kept) v = g_boxes_s[s_keep[tid]];
        reinterpret_cast<float4*>(out)[tid] = v;
    }
}

// ---------------- launch ----------------
extern "C" void kernel_launch(void* const* d_in, const int* in_sizes, int n_in,
                              void* d_out, int out_size)
{
    const float* anchors = (const float*)d_in[0];
    const float* cls     = (const float*)d_in[1];
    const float* reg     = (const float*)d_in[2];
    const int*   img_w   = (n_in > 3) ? (const int*)d_in[3] : nullptr;
    const int*   img_h   = (n_in > 4) ? (const int*)d_in[4] : nullptr;
    int have_wh = (n_in > 4) ? 1 : 0;

    decode_kernel<<<(N_ANCH + 255) / 256, 256>>>(anchors, cls, reg, img_w, img_h, have_wh);
    plan_kernel<<<1, 1024>>>();
    scatter_kernel<<<(N_ANCH + 255) / 256, 256>>>();
    rank_kernel<<<(N_ANCH + 255) / 256, 256>>>();
    mask_kernel<<<dim3(NWORDS, NWORDS), 64>>>();
    scan_kernel<<<1, 1024>>>((float*)d_out);
}

// round 7
// speedup vs baseline: 1.1305x; 1.1305x over previous
#include <cuda_runtime.h>
#include <cstdint>

#define N_ANCH 36864
#define PRE    6000
#define NWORDS 94      /* ceil(6000/64) */
#define POST   300
#define NMS_T  0.7f
#define NEG_INF_F (-1e9f)
#define NBINS  65536
#define BPT    64      /* bins per thread in plan kernel (65536/1024) */

// ---------------- scratch (static device globals; no allocation) ----------------
__device__ float4             g_boxes[N_ANCH];          // decoded+clipped boxes
__device__ unsigned long long g_keyfull[N_ANCH];        // (desc<<16)|idx
__device__ int                g_hist[NBINS];            // zero at load; plan re-zeroes
__device__ int                g_bin_base[NBINS];
__device__ int                g_bin_fill[NBINS];        // zero at load; plan re-zeroes
__device__ int                g_thresh_bin;
__device__ int                g_cand_total;
__device__ unsigned long long g_cand[N_ANCH];
__device__ float4             g_boxes_s[PRE];           // top-6000 boxes, score order
__device__ unsigned long long g_invalid_words[NWORDS];  // suppressed-at-start bits

// ---------------- 1. decode + clip + valid + key + histogram ----------------
__global__ void decode_kernel(const float* __restrict__ anchors,
                              const float* __restrict__ cls,
                              const float* __restrict__ reg,
                              const int* __restrict__ img_w_p,
                              const int* __restrict__ img_h_p,
                              int have_wh)
{
    int i = blockIdx.x * blockDim.x + threadIdx.x;
    if (i >= N_ANCH) return;

    float a0 = anchors[4*i+0], a1 = anchors[4*i+1];
    float a2 = anchors[4*i+2], a3 = anchors[4*i+3];
    float r0 = reg[4*i+0], r1 = reg[4*i+1], r2 = reg[4*i+2], r3 = reg[4*i+3];

    float w  = __fsub_rn(a2, a0);
    float h  = __fsub_rn(a3, a1);
    float cx = __fadd_rn(a0, __fmul_rn(0.5f, w));
    float cy = __fadd_rn(a1, __fmul_rn(0.5f, h));
    float pcx = __fadd_rn(__fmul_rn(r0, w), cx);
    float pcy = __fadd_rn(__fmul_rn(r1, h), cy);
    float pw  = __fmul_rn(expf(r2), w);
    float ph  = __fmul_rn(expf(r3), h);

    float b0 = __fsub_rn(pcx, __fmul_rn(0.5f, pw));
    float b1 = __fsub_rn(pcy, __fmul_rn(0.5f, ph));
    float b2 = __fadd_rn(pcx, __fmul_rn(0.5f, pw));
    float b3 = __fadd_rn(pcy, __fmul_rn(0.5f, ph));

    float H = have_wh ? (float)(*img_h_p) : 1024.0f;
    float W = have_wh ? (float)(*img_w_p) : 1024.0f;
    // reference: cols 0,2 clipped by img_h; cols 1,3 by img_w
    b0 = fminf(fmaxf(b0, 0.0f), H);
    b2 = fminf(fmaxf(b2, 0.0f), H);
    b1 = fminf(fmaxf(b1, 0.0f), W);
    b3 = fminf(fmaxf(b3, 0.0f), W);

    bool valid = (__fsub_rn(b2, b0) >= 16.0f) && (__fsub_rn(b3, b1) >= 16.0f);
    float s = valid ? cls[i] : NEG_INF_F;

    g_boxes[i] = make_float4(b0, b1, b2, b3);

    // stable descending sort key: smaller desc = higher score; idx breaks ties (stable)
    unsigned int bits = __float_as_uint(s);
    unsigned int asc  = (bits & 0x80000000u) ? ~bits : (bits | 0x80000000u);
    unsigned int desc = ~asc;
    unsigned long long key = ((unsigned long long)desc << 16) | (unsigned int)i;
    g_keyfull[i] = key;
    atomicAdd(&g_hist[desc >> 16], 1);
}

// ---------------- 2. plan: prefix-sum 65536 bins, find threshold, reset ----------------
__global__ void __launch_bounds__(1024) plan_kernel()
{
    __shared__ int sp[1024];
    __shared__ int s_thresh;
    int t = threadIdx.x;
    if (t == 0) s_thresh = 0x7FFFFFFF;

    int b0 = t * BPT;
    int sum = 0;
    for (int k = 0; k < BPT; k++) sum += g_hist[b0 + k];
    sp[t] = sum;
    __syncthreads();
    for (int off = 1; off < 1024; off <<= 1) {
        int v = (t >= off) ? sp[t - off] : 0;
        __syncthreads();
        sp[t] += v;
        __syncthreads();
    }
    int run = sp[t] - sum;                 // exclusive prefix for this thread's range
    bool straddle = (run < PRE) && (sp[t] >= PRE);
    for (int k = 0; k < BPT; k++) {
        int h = g_hist[b0 + k];            // re-read (L2 hit)
        g_bin_base[b0 + k] = run;
        run += h;
        if (straddle && run >= PRE && run - h < PRE) atomicMin(&s_thresh, b0 + k);
    }
    __syncthreads();
    if (t == 0) {
        int tb = s_thresh;
        g_thresh_bin = tb;
        g_cand_total = g_bin_base[tb] + g_hist[tb];
    }
    __syncthreads();   // t0 reads g_hist before zeroing
    for (int k = 0; k < BPT; k++) { g_hist[b0 + k] = 0; g_bin_fill[b0 + k] = 0; }
    if (t < NWORDS)
        g_invalid_words[t] = (t == NWORDS-1) ? ~((1ull << 48) - 1) : 0ull;  // ranks >= 6000
}

// ---------------- 3. scatter candidates into per-bin segments ----------------
__global__ void scatter_kernel()
{
    int i = blockIdx.x * blockDim.x + threadIdx.x;
    if (i >= N_ANCH) return;
    unsigned long long key = g_keyfull[i];
    int bin = (int)(key >> 32);
    if (bin <= g_thresh_bin) {
        int pos = g_bin_base[bin] + atomicAdd(&g_bin_fill[bin], 1);
        g_cand[pos] = key;
    }
}

// ---------------- 4. exact rank within bin + gather boxes ----------------
__global__ void rank_kernel()
{
    int c = blockIdx.x * blockDim.x + threadIdx.x;
    int tot = g_cand_total;
    if (c >= tot) return;
    unsigned long long key = g_cand[c];
    int bin = (int)(key >> 32);
    int b0 = g_bin_base[bin];
    int b1 = b0 + g_bin_fill[bin];
    int rank = b0;
    for (int j = b0; j < b1; j++)
        if (g_cand[j] < key) rank++;
    if (rank < PRE) {
        int idx = (int)(key & 0xFFFFull);
        g_boxes_s[rank] = g_boxes[idx];
        unsigned int desc = (unsigned int)(key >> 16);
        if (desc & 0x80000000u)   // invalid box -> pre-suppressed
            atomicOr(&g_invalid_words[rank >> 6], 1ull << (rank & 63));
    }
}

// ---------------- 5. fused greedy NMS (on-the-fly IoU vs kept boxes) ----------------
__device__ __forceinline__ int iou_gt(float4 a, float aa, float4 b, float ab)
{
    float xx1 = fmaxf(a.x, b.x);
    float yy1 = fmaxf(a.y, b.y);
    float xx2 = fminf(a.z, b.z);
    float yy2 = fminf(a.w, b.w);
    float iw  = fmaxf(__fsub_rn(xx2, xx1), 0.0f);
    float ih  = fmaxf(__fsub_rn(yy2, yy1), 0.0f);
    float inter = __fmul_rn(iw, ih);
    // exact reference op order: ((aa + ab) - inter) + 1e-9, IEEE divide
    float den = __fadd_rn(__fsub_rn(__fadd_rn(aa, ab), inter), 1e-9f);
    float iou = __fdiv_rn(inter, den);
    return iou > NMS_T;
}

__global__ void __launch_bounds__(1024) nms_kernel(float* __restrict__ out)
{
    __shared__ float4            s_kb[POST];       // kept boxes, score order
    __shared__ float             s_ka[POST];       // kept areas
    __shared__ float4            s_cb[64];         // current chunk boxes
    __shared__ float             s_ca[64];         // chunk areas
    __shared__ unsigned long long s_intra[64];     // intra-chunk suppression bits
    __shared__ unsigned long long s_sup;           // suppressed-by-earlier-kept bits
    __shared__ int s_kept;
    int tid = threadIdx.x;

    if (tid == 0) s_kept = 0;
    __syncthreads();

    for (int c = 0; c < NWORDS; c++) {
        // load chunk boxes + areas; clear masks
        if (tid < 64) {
            int i = c * 64 + tid;
            float4 b = (i < PRE) ? g_boxes_s[i] : make_float4(0.f, 0.f, 0.f, 0.f);
            s_cb[tid] = b;
            s_ca[tid] = __fmul_rn(__fsub_rn(b.z, b.x), __fsub_rn(b.w, b.y));
            s_intra[tid] = 0ull;
        }
        if (tid == 1024 - 1) s_sup = 0ull;
        int kept0 = s_kept;                       // stable: only t0 modifies, last sync read
        __syncthreads();

        // A) chunk boxes vs already-kept boxes  (64 * kept0 pairs)
        for (int p = tid; p < 64 * kept0; p += 1024) {
            int b = p & 63;
            int k = p >> 6;
            if (iou_gt(s_kb[k], s_ka[k], s_cb[b], s_ca[b]))
                atomicOr(&s_sup, 1ull << b);
        }
        // B) intra-chunk 64x64 upper triangle
        for (int p = tid; p < 64 * 64; p += 1024) {
            int i = p >> 6;
            int j = p & 63;
            if (j > i && iou_gt(s_cb[i], s_ca[i], s_cb[j], s_ca[j]))
                atomicOr(&s_intra[i], 1ull << j);
        }
        __syncthreads();

        // C) serial greedy walk for this chunk
        if (tid == 0) {
            unsigned long long rem = g_invalid_words[c] | s_sup;
            int kept = kept0;
            unsigned long long m = ~rem;
            while (m) {
                int b = __ffsll((long long)m) - 1;   // smallest alive index
                s_kb[kept] = s_cb[b];
                s_ka[kept] = s_ca[b];
                kept++;
                if (kept >= POST) break;
                rem |= s_intra[b];
                m = ~rem & (~0ull << (b + 1));
            }
            s_kept = kept;
        }
        __syncthreads();
        if (s_kept >= POST) break;                   // output fixed
    }
    __syncthreads();

    // write output: kept boxes in order, zero-pad the tail
    int kept = s_kept;
    if (tid < POST) {
        float4 v = make_float4(0.f, 0.f, 0.f, 0.f);
        if (tid < kept) v = s_kb[tid];
        reinterpret_cast<float4*>(out)[tid] = v;
    }
}

// ---------------- launch ----------------
extern "C" void kernel_launch(void* const* d_in, const int* in_sizes, int n_in,
                              void* d_out, int out_size)
{
    const float* anchors = (const float*)d_in[0];
    const float* cls     = (const float*)d_in[1];
    const float* reg     = (const float*)d_in[2];
    const int*   img_w   = (n_in > 3) ? (const int*)d_in[3] : nullptr;
    const int*   img_h   = (n_in > 4) ? (const int*)d_in[4] : nullptr;
    int have_wh = (n_in > 4) ? 1 : 0;

    decode_kernel<<<(N_ANCH + 255) / 256, 256>>>(anchors, cls, reg, img_w, img_h, have_wh);
    plan_kernel<<<1, 1024>>>();
    scatter_kernel<<<(N_ANCH + 255) / 256, 256>>>();
    rank_kernel<<<(N_ANCH + 255) / 256, 256>>>();
    nms_kernel<<<1, 1024>>>((float*)d_out);
}